// round 15
// baseline (speedup 1.0000x reference)
#include <cuda_runtime.h>
#include <string.h>

#define BSZ   16
#define NPTS  16384
#define NPOUT 1024
#define NSAMP 32
#define MROWS (BSZ*NPOUT*NSAMP)   /* 524288 */
#define NBLK  (MROWS/128)         /* 4096 */
#define XYZ_OUT (BSZ*3*NPOUT)     /* 49152 */

// ---------------- scratch (device globals; no runtime allocation) ----------------
__device__ float d_pT[(size_t)BSZ*NPTS*64];
__device__ float d_Y0[(size_t)MROWS*64];
__device__ float d_Y1[(size_t)MROWS*128];
__device__ float d_Y2[(size_t)MROWS*128];
__device__ float d_psum[NBLK*128];
__device__ float d_psq [NBLK*128];
__device__ float d_a0[64],  d_c0[64];
__device__ float d_a1[128], d_c1[128];
__device__ float d_a2[128], d_c2[128];

// ---------------- packed f32x2 helpers ----------------
static __device__ __forceinline__ float2 fadd2(float2 a, float2 b){
    unsigned long long ua, ub, ud;
    memcpy(&ua,&a,8); memcpy(&ub,&b,8);
    asm("add.rn.f32x2 %0, %1, %2;" : "=l"(ud) : "l"(ua), "l"(ub));
    float2 d; memcpy(&d,&ud,8); return d;
}
static __device__ __forceinline__ float2 fmul2(float2 a, float2 b){
    unsigned long long ua, ub, ud;
    memcpy(&ua,&a,8); memcpy(&ub,&b,8);
    asm("mul.rn.f32x2 %0, %1, %2;" : "=l"(ud) : "l"(ua), "l"(ub));
    float2 d; memcpy(&d,&ud,8); return d;
}
static __device__ __forceinline__ float2 ffma2(float2 a, float2 b, float2 c){
    unsigned long long ua, ub, uc, ud;
    memcpy(&ua,&a,8); memcpy(&ub,&b,8); memcpy(&uc,&c,8);
    asm("fma.rn.f32x2 %0, %1, %2, %3;" : "=l"(ud) : "l"(ua), "l"(ub), "l"(uc));
    float2 d; memcpy(&d,&ud,8); return d;
}

// ---------------- transpose points [B,64,N] -> [B,N,64] ----------------
__global__ void transpose_kernel(const float* __restrict__ pts, float* __restrict__ pT){
    __shared__ float t[32][33];
    int b = blockIdx.z, n0 = blockIdx.x*32, c0 = blockIdx.y*32;
    int tx = threadIdx.x, ty = threadIdx.y;
    #pragma unroll
    for (int i=0;i<4;i++)
        t[ty+i*8][tx] = pts[((size_t)b*64 + (c0+ty+i*8))*NPTS + n0 + tx];
    __syncthreads();
    #pragma unroll
    for (int i=0;i<4;i++)
        pT[((size_t)b*NPTS + (n0+ty+i*8))*64 + c0 + tx] = t[tx][ty+i*8];
}

// ---------------- FPS: 1 block/batch, writes new_xyz slice of output ----------------
#define FPS_SMEM (8192*8*2 + NPTS*4 + 3*32*4)
__global__ void __launch_bounds__(1024,1) fps_kernel(const float* __restrict__ xyz,
                                                     const int* __restrict__ fps_init,
                                                     float* __restrict__ out){
    extern __shared__ float sm[];
    float2* s_x2 = (float2*)sm;
    float2* s_y2 = s_x2 + 8192;
    float*  s_z  = (float*)(s_y2 + 8192);
    float*  s_rv = s_z + NPTS;
    int*    s_ri = (int*)(s_rv + 32);
    int*    s_wi = s_ri + 32;

    const int b = blockIdx.x, tid = threadIdx.x;
    const int lane = tid & 31, wid = tid >> 5;
    const float*  xb = xyz + (size_t)b*3*NPTS;
    const float2* xs = (const float2*)xb;
    const float2* ys = (const float2*)(xb + NPTS);
    const float2* zs = (const float2*)(xb + 2*NPTS);

    float2 zr[8], distr[8];
    #pragma unroll
    for (int j=0;j<8;j++){
        int p = j*1024 + tid;
        s_x2[p] = xs[p];
        s_y2[p] = ys[p];
        float2 z = zs[p];
        zr[j] = z;
        ((float2*)s_z)[p] = z;
        distr[j] = make_float2(1e10f, 1e10f);
    }
    __syncthreads();

    int far = fps_init[b];
    float* outx = out + (size_t)b*3*NPOUT;

    for (int t=0; t<NPOUT; t++){
        int fp = far >> 1, fh = far & 1;
        float2 vx = s_x2[fp], vy = s_y2[fp];
        float cx = fh ? vx.y : vx.x;
        float cy = fh ? vy.y : vy.x;
        float cz = s_z[far];
        if (tid == 0){ outx[t]=cx; outx[NPOUT+t]=cy; outx[2*NPOUT+t]=cz; }
        float2 NCX = make_float2(-cx,-cx), NCY = make_float2(-cy,-cy), NCZ = make_float2(-cz,-cz);

        float bv = -1.0f; int bi = 0;
        #pragma unroll
        for (int j=0;j<8;j++){
            int p = j*1024 + tid;
            float2 dx = fadd2(s_x2[p], NCX);
            float2 dy = fadd2(s_y2[p], NCY);
            float2 dz = fadd2(zr[j],   NCZ);
            // plain mul/add (no fma) to mimic jnp sum((x-c)**2) evaluation order
            float2 D = fadd2(fadd2(fmul2(dx,dx), fmul2(dy,dy)), fmul2(dz,dz));
            float d0 = fminf(distr[j].x, D.x);
            float d1 = fminf(distr[j].y, D.y);
            distr[j].x = d0; distr[j].y = d1;
            if (d0 > bv){ bv = d0; bi = 2*p; }
            if (d1 > bv){ bv = d1; bi = 2*p+1; }
        }
        #pragma unroll
        for (int off=16; off; off>>=1){
            float ov = __shfl_down_sync(0xffffffffu, bv, off);
            int   oi = __shfl_down_sync(0xffffffffu, bi, off);
            if (ov > bv || (ov == bv && oi < bi)){ bv = ov; bi = oi; }
        }
        if (lane == 0){ s_rv[wid] = bv; s_ri[wid] = bi; }
        __syncthreads();
        if (wid == 0){
            bv = s_rv[lane]; bi = s_ri[lane];
            #pragma unroll
            for (int off=16; off; off>>=1){
                float ov = __shfl_down_sync(0xffffffffu, bv, off);
                int   oi = __shfl_down_sync(0xffffffffu, bi, off);
                if (ov > bv || (ov == bv && oi < bi)){ bv = ov; bi = oi; }
            }
            if (lane == 0) s_wi[0] = bi;
        }
        __syncthreads();
        far = s_wi[0];
    }
}

// ---------------- GEMM0: gather(xyz,pT) -> Y0[M,64], K=67, bias + BN partials ----------------
#define G0_SMEM ((67*132 + 67*68 + 2*16*68)*4)
__global__ void __launch_bounds__(256,1) gemm0_kernel(const float* __restrict__ xyz,
                                                      const float* __restrict__ pT,
                                                      const int*   __restrict__ gidx,
                                                      const float* __restrict__ W,
                                                      const float* __restrict__ bias,
                                                      float* __restrict__ Yout,
                                                      float* __restrict__ psum,
                                                      float* __restrict__ psq){
    extern __shared__ float sm[];
    float* Xs   = sm;                 // [67][132]
    float* Ws   = Xs + 67*132;        // [67][68]
    float* s_ps = Ws + 67*68;         // [16][68]
    float* s_pq = s_ps + 16*68;       // [16][68]

    const int tid = threadIdx.x;
    const int m0  = blockIdx.x * 128;
    const int b   = m0 >> 15;          // 32768 rows per batch

    { // stage W: [64][67] -> Ws[k][o]
        int o = tid & 63, part = tid >> 6;
        int k0 = part*17, k1 = (part==3) ? 67 : k0+17;
        for (int k=k0;k<k1;k++) Ws[k*68+o] = W[o*67+k];
    }
    { // stage X via gather
        int r = tid >> 1, h = tid & 1;
        int idx = gidx[m0 + r];
        const float4* prow = (const float4*)(pT + ((size_t)b*NPTS + idx)*64) + h*8;
        #pragma unroll
        for (int q=0;q<8;q++){
            float4 v = prow[q];
            int k = 3 + h*32 + q*4;
            Xs[(k+0)*132+r]=v.x; Xs[(k+1)*132+r]=v.y;
            Xs[(k+2)*132+r]=v.z; Xs[(k+3)*132+r]=v.w;
        }
        if (h == 0){
            const float* xb = xyz + (size_t)b*3*NPTS;
            Xs[0*132+r] = xb[idx];
            Xs[1*132+r] = xb[NPTS + idx];
            Xs[2*132+r] = xb[2*NPTS + idx];
        }
    }
    __syncthreads();

    const int tx = tid & 15, ty = tid >> 4;
    const int ra = ty*4, rb = 64 + ty*4, ca = tx*4;
    float2 acc[8][2];
    #pragma unroll
    for (int i=0;i<8;i++){ acc[i][0]=make_float2(0,0); acc[i][1]=make_float2(0,0); }

    #pragma unroll 4
    for (int k=0;k<67;k++){
        float4 a0 = *(const float4*)(Xs + k*132 + ra);
        float4 a1 = *(const float4*)(Xs + k*132 + rb);
        float4 bq = *(const float4*)(Ws + k*68  + ca);
        float2 bp0 = make_float2(bq.x, bq.y), bp1 = make_float2(bq.z, bq.w);
        float av[8] = {a0.x,a0.y,a0.z,a0.w,a1.x,a1.y,a1.z,a1.w};
        #pragma unroll
        for (int i=0;i<8;i++){
            float2 ad = make_float2(av[i], av[i]);
            acc[i][0] = ffma2(ad, bp0, acc[i][0]);
            acc[i][1] = ffma2(ad, bp1, acc[i][1]);
        }
    }
    float bs0=bias[ca], bs1=bias[ca+1], bs2=bias[ca+2], bs3=bias[ca+3];
    float cs[4]={0,0,0,0}, cq[4]={0,0,0,0};
    #pragma unroll
    for (int i=0;i<8;i++){
        int r = (i<4) ? (ra+i) : (rb+i-4);
        float v0=acc[i][0].x+bs0, v1=acc[i][0].y+bs1, v2=acc[i][1].x+bs2, v3=acc[i][1].y+bs3;
        *(float4*)(Yout + (size_t)(m0+r)*64 + ca) = make_float4(v0,v1,v2,v3);
        cs[0]+=v0; cq[0]+=v0*v0; cs[1]+=v1; cq[1]+=v1*v1;
        cs[2]+=v2; cq[2]+=v2*v2; cs[3]+=v3; cq[3]+=v3*v3;
    }
    #pragma unroll
    for (int j=0;j<4;j++){ s_ps[ty*68+ca+j]=cs[j]; s_pq[ty*68+ca+j]=cq[j]; }
    __syncthreads();
    if (tid < 64){
        float S=0,Q=0;
        #pragma unroll
        for (int t=0;t<16;t++){ S += s_ps[t*68+tid]; Q += s_pq[t*68+tid]; }
        psum[blockIdx.x*64 + tid] = S;
        psq [blockIdx.x*64 + tid] = Q;
    }
}

// ---------------- GEMM mid (layers 1,2): x = relu(a*y+c) on load, N=128 ----------------
#define MID_SMEM(K) ((2*(K)*132 + 2*16*132 + 2*(K))*4)
template<int K>
__global__ void __launch_bounds__(256,1) gemm_mid_kernel(const float* __restrict__ Yin,
                                                         const float* __restrict__ W,
                                                         const float* __restrict__ bias,
                                                         const float* __restrict__ av,
                                                         const float* __restrict__ cv,
                                                         float* __restrict__ Yout,
                                                         float* __restrict__ psum,
                                                         float* __restrict__ psq){
    extern __shared__ float sm[];
    float* Xs   = sm;                   // [K][132]
    float* Ws   = Xs + K*132;           // [K][132]
    float* s_ps = Ws + K*132;           // [16][132]
    float* s_pq = s_ps + 16*132;        // [16][132]
    float* s_a  = s_pq + 16*132;        // [K]
    float* s_c  = s_a + K;              // [K]

    const int tid = threadIdx.x;
    const int m0  = blockIdx.x * 128;

    for (int k=tid; k<K; k+=256){ s_a[k]=av[k]; s_c[k]=cv[k]; }
    { // stage W [128][K] -> Ws[k][o]
        int o = tid >> 1, h = tid & 1;
        const float4* wr = (const float4*)(W + (size_t)o*K) + h*(K/8);
        #pragma unroll
        for (int q=0;q<K/8;q++){
            float4 v = wr[q];
            int k = h*(K/2) + q*4;
            Ws[(k+0)*132+o]=v.x; Ws[(k+1)*132+o]=v.y;
            Ws[(k+2)*132+o]=v.z; Ws[(k+3)*132+o]=v.w;
        }
    }
    __syncthreads();
    { // stage X with relu(a*y+c)
        int r = tid >> 1, h = tid & 1;
        const float4* yr = (const float4*)(Yin + (size_t)(m0+r)*K) + h*(K/8);
        #pragma unroll
        for (int q=0;q<K/8;q++){
            float4 v = yr[q];
            int k = h*(K/2) + q*4;
            Xs[(k+0)*132+r] = fmaxf(fmaf(s_a[k+0], v.x, s_c[k+0]), 0.f);
            Xs[(k+1)*132+r] = fmaxf(fmaf(s_a[k+1], v.y, s_c[k+1]), 0.f);
            Xs[(k+2)*132+r] = fmaxf(fmaf(s_a[k+2], v.z, s_c[k+2]), 0.f);
            Xs[(k+3)*132+r] = fmaxf(fmaf(s_a[k+3], v.w, s_c[k+3]), 0.f);
        }
    }
    __syncthreads();

    const int tx = tid & 15, ty = tid >> 4;
    const int ra = ty*4, rb = 64 + ty*4;
    const int ca = tx*4, cb = 64 + tx*4;
    float2 acc[8][4];
    #pragma unroll
    for (int i=0;i<8;i++)
        #pragma unroll
        for (int j=0;j<4;j++) acc[i][j]=make_float2(0,0);

    #pragma unroll 4
    for (int k=0;k<K;k++){
        float4 a0 = *(const float4*)(Xs + k*132 + ra);
        float4 a1 = *(const float4*)(Xs + k*132 + rb);
        float4 b0 = *(const float4*)(Ws + k*132 + ca);
        float4 b1 = *(const float4*)(Ws + k*132 + cb);
        float2 bp[4] = { make_float2(b0.x,b0.y), make_float2(b0.z,b0.w),
                         make_float2(b1.x,b1.y), make_float2(b1.z,b1.w) };
        float av8[8] = {a0.x,a0.y,a0.z,a0.w,a1.x,a1.y,a1.z,a1.w};
        #pragma unroll
        for (int i=0;i<8;i++){
            float2 ad = make_float2(av8[i], av8[i]);
            #pragma unroll
            for (int j=0;j<4;j++) acc[i][j] = ffma2(ad, bp[j], acc[i][j]);
        }
    }
    float bA[4] = {bias[ca],bias[ca+1],bias[ca+2],bias[ca+3]};
    float bB[4] = {bias[cb],bias[cb+1],bias[cb+2],bias[cb+3]};
    float cs[8]={0,0,0,0,0,0,0,0}, cq[8]={0,0,0,0,0,0,0,0};
    #pragma unroll
    for (int i=0;i<8;i++){
        int r = (i<4) ? (ra+i) : (rb+i-4);
        float v0=acc[i][0].x+bA[0], v1=acc[i][0].y+bA[1], v2=acc[i][1].x+bA[2], v3=acc[i][1].y+bA[3];
        float w0=acc[i][2].x+bB[0], w1=acc[i][2].y+bB[1], w2=acc[i][3].x+bB[2], w3=acc[i][3].y+bB[3];
        float* orow = Yout + (size_t)(m0+r)*128;
        *(float4*)(orow + ca) = make_float4(v0,v1,v2,v3);
        *(float4*)(orow + cb) = make_float4(w0,w1,w2,w3);
        cs[0]+=v0; cq[0]+=v0*v0; cs[1]+=v1; cq[1]+=v1*v1;
        cs[2]+=v2; cq[2]+=v2*v2; cs[3]+=v3; cq[3]+=v3*v3;
        cs[4]+=w0; cq[4]+=w0*w0; cs[5]+=w1; cq[5]+=w1*w1;
        cs[6]+=w2; cq[6]+=w2*w2; cs[7]+=w3; cq[7]+=w3*w3;
    }
    #pragma unroll
    for (int j=0;j<4;j++){
        s_ps[ty*132+ca+j]=cs[j];   s_pq[ty*132+ca+j]=cq[j];
        s_ps[ty*132+cb+j]=cs[4+j]; s_pq[ty*132+cb+j]=cq[4+j];
    }
    __syncthreads();
    if (tid < 128){
        float S=0,Q=0;
        #pragma unroll
        for (int t=0;t<16;t++){ S += s_ps[t*132+tid]; Q += s_pq[t*132+tid]; }
        psum[blockIdx.x*128 + tid] = S;
        psq [blockIdx.x*128 + tid] = Q;
    }
}

// ---------------- BN finalize: a = g*rsqrt(var+eps), c = be - m*a ----------------
__global__ void finalize_kernel(const float* __restrict__ psum, const float* __restrict__ psq,
                                const float* __restrict__ g, const float* __restrict__ be,
                                float* __restrict__ aout, float* __restrict__ cout_, int C){
    __shared__ float ss[256], sq[256];
    int ch = blockIdx.x, tid = threadIdx.x;
    float S=0,Q=0;
    for (int i=tid; i<NBLK; i+=256){ S += psum[i*C+ch]; Q += psq[i*C+ch]; }
    ss[tid]=S; sq[tid]=Q; __syncthreads();
    for (int s=128; s; s>>=1){
        if (tid < s){ ss[tid]+=ss[tid+s]; sq[tid]+=sq[tid+s]; }
        __syncthreads();
    }
    if (tid == 0){
        const float inv = 1.0f/524288.0f;
        float m = ss[0]*inv;
        float var = sq[0]*inv - m*m;
        float a = g[ch]*rsqrtf(var + 1e-5f);
        aout[ch] = a;
        cout_[ch] = be[ch] - m*a;
    }
}

// ---------------- final: norm+relu+max over NSAMP, write new_points ----------------
__global__ void __launch_bounds__(128,8) maxpool_kernel(const float* __restrict__ Y2,
                                                        const float* __restrict__ av,
                                                        const float* __restrict__ cv,
                                                        float* __restrict__ out){
    int gid = blockIdx.x;       // b*NPOUT + s
    int ch  = threadIdx.x;
    const float* base = Y2 + (size_t)gid*NSAMP*128 + ch;
    float a = __ldg(av+ch), c = __ldg(cv+ch);
    float m = 0.0f;             // relu clamps at 0: max(relu(v)) == max(0, max(v))
    #pragma unroll 8
    for (int r=0;r<NSAMP;r++)
        m = fmaxf(m, fmaf(a, base[(size_t)r*128], c));
    int b = gid >> 10, s = gid & 1023;
    out[(size_t)XYZ_OUT + ((size_t)(b*128 + ch))*NPOUT + s] = m;
}

// ---------------- launch ----------------
extern "C" void kernel_launch(void* const* d_in, const int* in_sizes, int n_in,
                              void* d_out, int out_size){
    const float* xyz  = (const float*)d_in[0];
    const float* pts  = (const float*)d_in[1];
    const int*   fpsI = (const int*)d_in[2];
    const int*   gidx = (const int*)d_in[3];
    const float *W0=(const float*)d_in[4],  *bb0=(const float*)d_in[5];
    const float *g0=(const float*)d_in[6],  *be0=(const float*)d_in[7];
    const float *W1=(const float*)d_in[8],  *bb1=(const float*)d_in[9];
    const float *g1=(const float*)d_in[10], *be1=(const float*)d_in[11];
    const float *W2=(const float*)d_in[12], *bb2=(const float*)d_in[13];
    const float *g2=(const float*)d_in[14], *be2=(const float*)d_in[15];
    float* out = (float*)d_out;

    float *pT,*Y0,*Y1,*Y2,*ps,*pq,*a0,*c0,*a1,*c1,*a2,*c2;
    cudaGetSymbolAddress((void**)&pT, d_pT);
    cudaGetSymbolAddress((void**)&Y0, d_Y0);
    cudaGetSymbolAddress((void**)&Y1, d_Y1);
    cudaGetSymbolAddress((void**)&Y2, d_Y2);
    cudaGetSymbolAddress((void**)&ps, d_psum);
    cudaGetSymbolAddress((void**)&pq, d_psq);
    cudaGetSymbolAddress((void**)&a0, d_a0);  cudaGetSymbolAddress((void**)&c0, d_c0);
    cudaGetSymbolAddress((void**)&a1, d_a1);  cudaGetSymbolAddress((void**)&c1, d_c1);
    cudaGetSymbolAddress((void**)&a2, d_a2);  cudaGetSymbolAddress((void**)&c2, d_c2);

    cudaFuncSetAttribute(fps_kernel,   cudaFuncAttributeMaxDynamicSharedMemorySize, FPS_SMEM);
    cudaFuncSetAttribute(gemm0_kernel, cudaFuncAttributeMaxDynamicSharedMemorySize, G0_SMEM);
    cudaFuncSetAttribute(gemm_mid_kernel<64>,  cudaFuncAttributeMaxDynamicSharedMemorySize, MID_SMEM(64));
    cudaFuncSetAttribute(gemm_mid_kernel<128>, cudaFuncAttributeMaxDynamicSharedMemorySize, MID_SMEM(128));

    transpose_kernel<<<dim3(NPTS/32, 2, BSZ), dim3(32,8)>>>(pts, pT);
    fps_kernel<<<BSZ, 1024, FPS_SMEM>>>(xyz, fpsI, out);

    gemm0_kernel<<<NBLK, 256, G0_SMEM>>>(xyz, pT, gidx, W0, bb0, Y0, ps, pq);
    finalize_kernel<<<64, 256>>>(ps, pq, g0, be0, a0, c0, 64);

    gemm_mid_kernel<64><<<NBLK, 256, MID_SMEM(64)>>>(Y0, W1, bb1, a0, c0, Y1, ps, pq);
    finalize_kernel<<<128, 256>>>(ps, pq, g1, be1, a1, c1, 128);

    gemm_mid_kernel<128><<<NBLK, 256, MID_SMEM(128)>>>(Y1, W2, bb2, a1, c1, Y2, ps, pq);
    finalize_kernel<<<128, 256>>>(ps, pq, g2, be2, a2, c2, 128);

    maxpool_kernel<<<BSZ*NPOUT, 128>>>(Y2, a2, c2, out);
}